// round 1
// baseline (speedup 1.0000x reference)
#include <cuda_runtime.h>
#include <cstdint>

// ---------------- problem constants ----------------
constexpr int kS    = 65536;
constexpr int kM    = 256;
constexpr int kE    = 8;
constexpr int kH    = 1024;
constexpr int kCAP  = 20480;            // TOP_K * int(1.25 * ceil(S/E)) = 2*10240
constexpr int kECAP = kE * kCAP;        // 163840
constexpr int kNB   = 256;              // gating blocks (256 tokens each)

// ---------------- device scratch (static; no allocations) ----------------
__device__ int   g_topi[kS * 2];
__device__ float g_topv[kS * 2];
__device__ float g_wcomb[kS * 2];
__device__ int   g_slot[kS * 2];
__device__ int   g_src[kECAP];                    // slot -> source token (-1 = empty)
__device__ int   g_bcnt[kNB][2][kE];
__device__ int   g_boff[kNB][2][kE];
__device__ int   g_k0tot[kE];
__device__ float g_mepart[kNB][kE];
__device__ float g_h[(size_t)kECAP * kH];         // 640 MB hidden activations
__device__ float g_eo[(size_t)kECAP * kM];        // 160 MB expert outputs

// ---------------- K0: init slot->src map ----------------
__global__ void k_init() {
    int i = blockIdx.x * blockDim.x + threadIdx.x;
    if (i < kECAP) g_src[i] = -1;
}

// ---------------- K1: gating (logits, softmax, top-2, block counts, me partials) ----------------
__global__ void __launch_bounds__(256) k_gate(const float* __restrict__ x,
                                              const float* __restrict__ wg) {
    __shared__ float s_wg[kE * kM];       // 8 KB
    __shared__ float s_g[256][kE];        // 8 KB (per-token gate values for me)
    __shared__ int   s_cnt[2][kE];

    const int tid = threadIdx.x;
    const int blk = blockIdx.x;
    for (int i = tid; i < kE * kM; i += 256) s_wg[i] = wg[i];
    if (tid < 16) s_cnt[tid >> 3][tid & 7] = 0;
    __syncthreads();

    const int w = tid >> 5, lane = tid & 31;
    for (int i = 0; i < 32; ++i) {
        const int s = blk * 256 + w * 32 + i;
        const float4* xr = (const float4*)(x + (size_t)s * kM);
        const float4 a = xr[lane * 2];
        const float4 b = xr[lane * 2 + 1];
        float p[kE];
        #pragma unroll
        for (int e = 0; e < kE; ++e) {
            const float4* wr = (const float4*)(s_wg + e * kM);
            const float4 wa = wr[lane * 2], wb = wr[lane * 2 + 1];
            p[e] = a.x * wa.x + a.y * wa.y + a.z * wa.z + a.w * wa.w
                 + b.x * wb.x + b.y * wb.y + b.z * wb.z + b.w * wb.w;
        }
        #pragma unroll
        for (int off = 16; off; off >>= 1) {
            #pragma unroll
            for (int e = 0; e < kE; ++e) p[e] += __shfl_xor_sync(0xffffffffu, p[e], off);
        }
        // softmax over 8 (all lanes redundantly)
        float mx = p[0];
        #pragma unroll
        for (int e = 1; e < kE; ++e) mx = fmaxf(mx, p[e]);
        float g[kE]; float sum = 0.f;
        #pragma unroll
        for (int e = 0; e < kE; ++e) { g[e] = expf(p[e] - mx); sum += g[e]; }
        const float inv = 1.f / sum;
        #pragma unroll
        for (int e = 0; e < kE; ++e) g[e] *= inv;
        // top-2 (ties: lower index first, matching lax.top_k)
        float bv = -1.f; int bi = 0; float sv = -1.f; int si = 0;
        #pragma unroll
        for (int e = 0; e < kE; ++e) {
            const float ge = g[e];
            if (ge > bv) { sv = bv; si = bi; bv = ge; bi = e; }
            else if (ge > sv) { sv = ge; si = e; }
        }
        if (lane < kE) s_g[w * 32 + i][lane] = g[lane];
        if (lane == 0) {
            g_topi[2 * s]     = bi;  g_topi[2 * s + 1] = si;
            g_topv[2 * s]     = bv;  g_topv[2 * s + 1] = sv;
            atomicAdd(&s_cnt[0][bi], 1);
            atomicAdd(&s_cnt[1][si], 1);
        }
    }
    __syncthreads();
    if (tid < 16) g_bcnt[blk][tid >> 3][tid & 7] = s_cnt[tid >> 3][tid & 7];
    if (tid < kE) {                                  // deterministic serial sum
        float acc = 0.f;
        for (int t = 0; t < 256; ++t) acc += s_g[t][tid];
        g_mepart[blk][tid] = acc;
    }
}

// ---------------- K2: scan block counts, totals, aux loss ----------------
__global__ void k_scan(float* __restrict__ out, int out_size) {
    __shared__ float s_me[kE];
    __shared__ int   s_t0[kE];
    const int tid = threadIdx.x;
    if (tid < 16) {
        const int k = tid >> 3, e = tid & 7;
        int run = 0;
        for (int b = 0; b < kNB; ++b) {
            const int t = g_bcnt[b][k][e];
            g_boff[b][k][e] = run;
            run += t;
        }
        if (k == 0) { g_k0tot[e] = run; s_t0[e] = run; }
    }
    if (tid >= 32 && tid < 32 + kE) {
        const int e = tid - 32;
        float acc = 0.f;
        for (int b = 0; b < kNB; ++b) acc += g_mepart[b][e];
        s_me[e] = acc;
    }
    __syncthreads();
    if (tid == 0 && out_size > kS * kM) {
        float loss = 0.f;
        #pragma unroll
        for (int e = 0; e < kE; ++e)
            loss += (s_me[e] / (float)kS) * ((float)s_t0[e] / (float)kS);
        out[(size_t)kS * kM] = loss * (float)kE;
    }
}

// ---------------- K3: exact stable locations, slots, inverse map ----------------
__global__ void __launch_bounds__(256) k_locs() {
    __shared__ int s_wtot[8][16];
    const int tid = threadIdx.x, blk = blockIdx.x;
    const int w = tid >> 5, lane = tid & 31;
    const int s = blk * 256 + tid;
    int idx[2] = { g_topi[2 * s], g_topi[2 * s + 1] };
    int rank[2] = { 0, 0 };
    #pragma unroll
    for (int k = 0; k < 2; ++k) {
        #pragma unroll
        for (int e = 0; e < kE; ++e) {
            const unsigned bal = __ballot_sync(0xffffffffu, idx[k] == e);
            if (lane == 0) s_wtot[w][k * 8 + e] = __popc(bal);
            if (idx[k] == e) rank[k] = __popc(bal & ((1u << lane) - 1u));
        }
    }
    __syncthreads();
    if (tid < 16) {
        int run = 0;
        for (int ww = 0; ww < 8; ++ww) {
            const int t = s_wtot[ww][tid];
            s_wtot[ww][tid] = run;
            run += t;
        }
    }
    __syncthreads();
    #pragma unroll
    for (int k = 0; k < 2; ++k) {
        const int e = idx[k];
        const int loc = g_boff[blk][k][e] + s_wtot[w][k * 8 + e] + rank[k]
                      + (k ? g_k0tot[e] : 0);
        const bool valid = loc < kCAP;
        const int slot = e * kCAP + (loc < kCAP - 1 ? loc : kCAP - 1);
        g_slot[2 * s + k]  = slot;
        g_wcomb[2 * s + k] = valid ? g_topv[2 * s + k] : 0.f;
        if (valid) g_src[slot] = s;
    }
}

// ---------------- K4/K5: 128x128x8 SGEMM (gather-fused A for phase 1) ----------------
// FIRST:  g_h[r, 0:1024] = relu( gather_x[r, 0:256] @ w1[e] + b1[e] )
// !FIRST: g_eo[r, 0:256] =        g_h[r, 0:1024]     @ w2[e] + b2[e]
template <bool FIRST>
__global__ void __launch_bounds__(256, 2) k_ffn(const float* __restrict__ X,
                                                const float* __restrict__ W,
                                                const float* __restrict__ bias) {
    constexpr int K = FIRST ? kM : kH;
    constexpr int N = FIRST ? kH : kM;
    __shared__ float As[8][128];
    __shared__ float Bs[8][128];
    __shared__ int   s_src[128];

    const int tid  = threadIdx.x;
    const int row0 = blockIdx.y * 128;
    const int n0   = blockIdx.x * 128;
    const int e    = row0 / kCAP;                 // CAP % 128 == 0, tiles never straddle
    const float* Bp    = W + (size_t)e * K * N;
    const float* biasE = bias + (size_t)e * N;

    if (FIRST) {
        if (tid < 128) s_src[tid] = g_src[row0 + tid];
        __syncthreads();
    }

    const int ar = tid >> 1, ac = (tid & 1) * 4;  // A: 128 rows x 8 k
    const int br = tid >> 5, bc = (tid & 31) * 4; // B: 8 k x 128 n
    const int tx = tid & 15, ty = tid >> 4;

    const float* arowp;
    if (FIRST) {
        const int si = s_src[ar];
        arowp = (si >= 0) ? (X + (size_t)si * K) : nullptr;
    } else {
        arowp = g_h + (size_t)(row0 + ar) * K;
    }

    float acc[8][8] = {};
    for (int k0 = 0; k0 < K; k0 += 8) {
        float4 av = make_float4(0.f, 0.f, 0.f, 0.f);
        if (!FIRST || arowp) av = *(const float4*)(arowp + k0 + ac);
        As[ac + 0][ar] = av.x; As[ac + 1][ar] = av.y;
        As[ac + 2][ar] = av.z; As[ac + 3][ar] = av.w;
        *(float4*)&Bs[br][bc] = *(const float4*)(Bp + (size_t)(k0 + br) * N + n0 + bc);
        __syncthreads();
        #pragma unroll
        for (int k = 0; k < 8; ++k) {
            const float4 a0 = *(const float4*)&As[k][ty * 8];
            const float4 a1 = *(const float4*)&As[k][ty * 8 + 4];
            const float4 b0 = *(const float4*)&Bs[k][tx * 8];
            const float4 b1 = *(const float4*)&Bs[k][tx * 8 + 4];
            const float am[8] = { a0.x, a0.y, a0.z, a0.w, a1.x, a1.y, a1.z, a1.w };
            const float bn[8] = { b0.x, b0.y, b0.z, b0.w, b1.x, b1.y, b1.z, b1.w };
            #pragma unroll
            for (int i = 0; i < 8; ++i)
                #pragma unroll
                for (int j = 0; j < 8; ++j)
                    acc[i][j] += am[i] * bn[j];
        }
        __syncthreads();
    }

    float bb[8];
    #pragma unroll
    for (int j = 0; j < 8; ++j) bb[j] = biasE[n0 + tx * 8 + j];
    float* Cbase = FIRST ? g_h : g_eo;
    #pragma unroll
    for (int i = 0; i < 8; ++i) {
        float v[8];
        #pragma unroll
        for (int j = 0; j < 8; ++j) {
            float t = acc[i][j] + bb[j];
            if (FIRST) t = fmaxf(t, 0.f);
            v[j] = t;
        }
        float* crow = Cbase + (size_t)(row0 + ty * 8 + i) * N + n0 + tx * 8;
        *(float4*)crow       = make_float4(v[0], v[1], v[2], v[3]);
        *((float4*)crow + 1) = make_float4(v[4], v[5], v[6], v[7]);
    }
}

// ---------------- K6: combine y[s] = w0*eo[slot0] + w1*eo[slot1] ----------------
__global__ void __launch_bounds__(256) k_combine(float* __restrict__ y) {
    const int tid = threadIdx.x, w = tid >> 5, lane = tid & 31;
    const int s = blockIdx.x * 8 + w;
    const int sl0 = g_slot[2 * s], sl1 = g_slot[2 * s + 1];
    const float w0 = g_wcomb[2 * s], w1 = g_wcomb[2 * s + 1];
    const float4* e0 = (const float4*)(g_eo + (size_t)sl0 * kM);
    const float4* e1 = (const float4*)(g_eo + (size_t)sl1 * kM);
    float4* yr = (float4*)(y + (size_t)s * kM);
    #pragma unroll
    for (int r = 0; r < 2; ++r) {
        const int j = lane * 2 + r;
        const float4 u = e0[j], v = e1[j];
        yr[j] = make_float4(w0 * u.x + w1 * v.x, w0 * u.y + w1 * v.y,
                            w0 * u.z + w1 * v.z, w0 * u.w + w1 * v.w);
    }
}

// ---------------- launcher ----------------
extern "C" void kernel_launch(void* const* d_in, const int* in_sizes, int n_in,
                              void* d_out, int out_size) {
    const float* x  = (const float*)d_in[0];
    const float* wg = (const float*)d_in[1];
    const float* w1 = (const float*)d_in[2];
    const float* b1 = (const float*)d_in[3];
    const float* w2 = (const float*)d_in[4];
    const float* b2 = (const float*)d_in[5];
    float* out = (float*)d_out;

    k_init<<<kECAP / 256, 256>>>();
    k_gate<<<kNB, 256>>>(x, wg);
    k_scan<<<1, 256>>>(out, out_size);
    k_locs<<<kNB, 256>>>();

    dim3 g1(kH / 128, kECAP / 128);   // (8, 1280)
    k_ffn<true><<<g1, 256>>>(x, w1, b1);
    dim3 g2(kM / 128, kECAP / 128);   // (2, 1280)
    k_ffn<false><<<g2, 256>>>(nullptr, w2, b2);

    k_combine<<<kS / 8, 256>>>(out);
}

// round 7
// speedup vs baseline: 1.8211x; 1.8211x over previous
#include <cuda_runtime.h>
#include <cuda_bf16.h>
#include <cstdint>

// ---------------- problem constants ----------------
constexpr int kS    = 65536;
constexpr int kM    = 256;
constexpr int kE    = 8;
constexpr int kH    = 1024;
constexpr int kCAP  = 20480;
constexpr int kECAP = kE * kCAP;     // 163840
constexpr int kNB   = 256;

// ---------------- device scratch (same profile as round 1) ----------------
__device__ int   g_topi[kS * 2];
__device__ float g_topv[kS * 2];
__device__ float g_wcomb[kS * 2];
__device__ int   g_slot[kS * 2];
__device__ int   g_src[kECAP];
__device__ int   g_bcnt[kNB][2][kE];
__device__ int   g_boff[kNB][2][kE];
__device__ int   g_k0tot[kE];
__device__ float g_mepart[kNB][kE];
__device__ __align__(16) float g_h[(size_t)kECAP * kH];   // 640 MB fp32 hidden
__device__ __align__(16) float g_eo[(size_t)kECAP * kM];  // 160 MB expert out

// ---------------- helpers ----------------
__device__ __forceinline__ uint32_t smem_u32(const void* p) {
    uint32_t a;
    asm("{ .reg .u64 t; cvta.to.shared.u64 t, %1; cvt.u32.u64 %0, t; }" : "=r"(a) : "l"(p));
    return a;
}

#define LDSM4(r0_, r1_, r2_, r3_, addr_)                                          \
    asm volatile("ldmatrix.sync.aligned.m8n8.x4.shared.b16 {%0,%1,%2,%3}, [%4];"  \
                 : "=r"(r0_), "=r"(r1_), "=r"(r2_), "=r"(r3_) : "r"(addr_))
#define LDSM4T(r0_, r1_, r2_, r3_, addr_)                                              \
    asm volatile("ldmatrix.sync.aligned.m8n8.x4.trans.shared.b16 {%0,%1,%2,%3}, [%4];" \
                 : "=r"(r0_), "=r"(r1_), "=r"(r2_), "=r"(r3_) : "r"(addr_))

#define MMA_T(mt_, nt_)                                                           \
    asm volatile("mma.sync.aligned.m16n8k16.row.col.f32.bf16.bf16.f32 "           \
                 "{%0,%1,%2,%3}, {%4,%5,%6,%7}, {%8,%9}, {%0,%1,%2,%3};"          \
                 : "+f"(c##mt_##_##nt_##_0), "+f"(c##mt_##_##nt_##_1),            \
                   "+f"(c##mt_##_##nt_##_2), "+f"(c##mt_##_##nt_##_3)             \
                 : "r"(a0), "r"(a1), "r"(a2), "r"(a3),                            \
                   "r"(b##nt_##_0), "r"(b##nt_##_1))

#define MMA_ALLNT(mt_) do { MMA_T(mt_,0); MMA_T(mt_,1); MMA_T(mt_,2); MMA_T(mt_,3); \
                            MMA_T(mt_,4); MMA_T(mt_,5); MMA_T(mt_,6); MMA_T(mt_,7); } while (0)

#define US16(h_) ((uint32_t)__bfloat16_as_ushort(h_))
// split one float4 into bf16-hi (8B) and bf16-lo (8B), store to two smem regions
#define STS_SPLIT(v_, off_, baseH_, baseL_) do {                                  \
    const __nv_bfloat16 H0_ = __float2bfloat16((v_).x);                           \
    const __nv_bfloat16 H1_ = __float2bfloat16((v_).y);                           \
    const __nv_bfloat16 H2_ = __float2bfloat16((v_).z);                           \
    const __nv_bfloat16 H3_ = __float2bfloat16((v_).w);                           \
    const __nv_bfloat16 L0_ = __float2bfloat16((v_).x - __bfloat162float(H0_));   \
    const __nv_bfloat16 L1_ = __float2bfloat16((v_).y - __bfloat162float(H1_));   \
    const __nv_bfloat16 L2_ = __float2bfloat16((v_).z - __bfloat162float(H2_));   \
    const __nv_bfloat16 L3_ = __float2bfloat16((v_).w - __bfloat162float(H3_));   \
    uint2 hu_, lu_;                                                               \
    hu_.x = US16(H0_) | (US16(H1_) << 16); hu_.y = US16(H2_) | (US16(H3_) << 16); \
    lu_.x = US16(L0_) | (US16(L1_) << 16); lu_.y = US16(L2_) | (US16(L3_) << 16); \
    *(uint2*)((baseH_) + (off_)) = hu_;                                           \
    *(uint2*)((baseL_) + (off_)) = lu_;                                           \
} while (0)

// ---------------- K0: init ----------------
__global__ void k_init() {
    int i = blockIdx.x * blockDim.x + threadIdx.x;
    if (i < kECAP) g_src[i] = -1;
}

// ---------------- K1: gating (unchanged from round 1) ----------------
__global__ void __launch_bounds__(256) k_gate(const float* __restrict__ x,
                                              const float* __restrict__ wg) {
    __shared__ float s_wg[kE * kM];
    __shared__ float s_g[256][kE];
    __shared__ int   s_cnt[2][kE];
    const int tid = threadIdx.x, blk = blockIdx.x;
    for (int i = tid; i < kE * kM; i += 256) s_wg[i] = wg[i];
    if (tid < 16) s_cnt[tid >> 3][tid & 7] = 0;
    __syncthreads();
    const int w = tid >> 5, lane = tid & 31;
    for (int i = 0; i < 32; ++i) {
        const int s = blk * 256 + w * 32 + i;
        const float4* xr = (const float4*)(x + (size_t)s * kM);
        const float4 a = xr[lane * 2];
        const float4 b = xr[lane * 2 + 1];
        float p[kE];
        #pragma unroll
        for (int e = 0; e < kE; ++e) {
            const float4* wr = (const float4*)(s_wg + e * kM);
            const float4 wa = wr[lane * 2], wb = wr[lane * 2 + 1];
            p[e] = a.x * wa.x + a.y * wa.y + a.z * wa.z + a.w * wa.w
                 + b.x * wb.x + b.y * wb.y + b.z * wb.z + b.w * wb.w;
        }
        #pragma unroll
        for (int off = 16; off; off >>= 1) {
            #pragma unroll
            for (int e = 0; e < kE; ++e) p[e] += __shfl_xor_sync(0xffffffffu, p[e], off);
        }
        float mx = p[0];
        #pragma unroll
        for (int e = 1; e < kE; ++e) mx = fmaxf(mx, p[e]);
        float g[kE]; float sum = 0.f;
        #pragma unroll
        for (int e = 0; e < kE; ++e) { g[e] = expf(p[e] - mx); sum += g[e]; }
        const float inv = 1.f / sum;
        #pragma unroll
        for (int e = 0; e < kE; ++e) g[e] *= inv;
        float bv = -1.f; int bi = 0; float sv = -1.f; int si = 0;
        #pragma unroll
        for (int e = 0; e < kE; ++e) {
            const float ge = g[e];
            if (ge > bv) { sv = bv; si = bi; bv = ge; bi = e; }
            else if (ge > sv) { sv = ge; si = e; }
        }
        if (lane < kE) s_g[w * 32 + i][lane] = g[lane];
        if (lane == 0) {
            g_topi[2 * s] = bi;  g_topi[2 * s + 1] = si;
            g_topv[2 * s] = bv;  g_topv[2 * s + 1] = sv;
            atomicAdd(&s_cnt[0][bi], 1);
            atomicAdd(&s_cnt[1][si], 1);
        }
    }
    __syncthreads();
    if (tid < 16) g_bcnt[blk][tid >> 3][tid & 7] = s_cnt[tid >> 3][tid & 7];
    if (tid < kE) {
        float acc = 0.f;
        for (int t = 0; t < 256; ++t) acc += s_g[t][tid];
        g_mepart[blk][tid] = acc;
    }
}

// ---------------- K2: scan + loss ----------------
__global__ void k_scan(float* __restrict__ out, int out_size) {
    __shared__ float s_me[kE];
    __shared__ int   s_t0[kE];
    const int tid = threadIdx.x;
    if (tid < 16) {
        const int k = tid >> 3, e = tid & 7;
        int run = 0;
        for (int b = 0; b < kNB; ++b) { const int t = g_bcnt[b][k][e]; g_boff[b][k][e] = run; run += t; }
        if (k == 0) { g_k0tot[e] = run; s_t0[e] = run; }
    }
    if (tid >= 32 && tid < 32 + kE) {
        const int e = tid - 32;
        float acc = 0.f;
        for (int b = 0; b < kNB; ++b) acc += g_mepart[b][e];
        s_me[e] = acc;
    }
    __syncthreads();
    if (tid == 0 && out_size > kS * kM) {
        float loss = 0.f;
        #pragma unroll
        for (int e = 0; e < kE; ++e)
            loss += (s_me[e] / (float)kS) * ((float)s_t0[e] / (float)kS);
        out[(size_t)kS * kM] = loss * (float)kE;
    }
}

// ---------------- K3: locations ----------------
__global__ void __launch_bounds__(256) k_locs() {
    __shared__ int s_wtot[8][16];
    const int tid = threadIdx.x, blk = blockIdx.x;
    const int w = tid >> 5, lane = tid & 31;
    const int s = blk * 256 + tid;
    int idx[2] = { g_topi[2 * s], g_topi[2 * s + 1] };
    int rank[2] = { 0, 0 };
    #pragma unroll
    for (int k = 0; k < 2; ++k)
        #pragma unroll
        for (int e = 0; e < kE; ++e) {
            const unsigned bal = __ballot_sync(0xffffffffu, idx[k] == e);
            if (lane == 0) s_wtot[w][k * 8 + e] = __popc(bal);
            if (idx[k] == e) rank[k] = __popc(bal & ((1u << lane) - 1u));
        }
    __syncthreads();
    if (tid < 16) {
        int run = 0;
        for (int ww = 0; ww < 8; ++ww) { const int t = s_wtot[ww][tid]; s_wtot[ww][tid] = run; run += t; }
    }
    __syncthreads();
    #pragma unroll
    for (int k = 0; k < 2; ++k) {
        const int e = idx[k];
        const int loc = g_boff[blk][k][e] + s_wtot[w][k * 8 + e] + rank[k] + (k ? g_k0tot[e] : 0);
        const bool valid = loc < kCAP;
        const int slot = e * kCAP + (loc < kCAP - 1 ? loc : kCAP - 1);
        g_slot[2 * s + k]  = slot;
        g_wcomb[2 * s + k] = valid ? g_topv[2 * s + k] : 0.f;
        if (valid) g_src[slot] = s;
    }
}

// ---------------- K4: mma GEMM, round-1 infrastructure ----------------
// CTA 128x128, 256 threads (4m x 2n warps, warp tile 32x64), k-chunk 32.
// Static smem: Ah/Al [128][32] bf16 (8KB each), Bh/Bl [32 k][128 n] bf16 (8KB each).
// fp32 sources split to bf16 hi/lo in registers during staging. 3-pass compensated MMA.
template <bool FIRST>
__global__ void __launch_bounds__(256) k_ffn_mma(const float* __restrict__ W,
                                                 const float* __restrict__ bias,
                                                 const float* __restrict__ x) {
    constexpr int K  = FIRST ? kM : kH;   // reduction dim
    constexpr int NF = FIRST ? kH : kM;   // output cols
    constexpr int NC = K / 32;

    __shared__ __align__(128) char sAh[8192];
    __shared__ __align__(128) char sAl[8192];
    __shared__ __align__(128) char sBh[8192];
    __shared__ __align__(128) char sBl[8192];
    __shared__ int s_src[128];

    const int tid = threadIdx.x;
    const int wid = tid >> 5, lane = tid & 31;
    const int wm = wid & 3, wn = wid >> 2;        // 4x2 warp grid, warp tile 32x64
    const int row0 = blockIdx.y * 128;
    const int n0   = blockIdx.x * 128;
    const int e    = row0 / kCAP;

    if (FIRST) {
        if (tid < 128) s_src[tid] = g_src[row0 + tid];
        __syncthreads();
    }

    // ---- staging assignment ----
    // A: row r = tid>>1 (2 thr/row), k = (tid&1)*16 + {0,4,8,12}
    // B: krow = tid>>3 (8 thr/row), n = (tid&7)*16 + {0,4,8,12}
    const int ar  = tid >> 1;
    const int kA  = (tid & 1) * 16;
    const int bkr = tid >> 3;
    const int bnb = (tid & 7) * 16;

    const int arx = (ar >> 1) & 3;
    const int ac0 = (tid & 1) * 2;
    const uint32_t aoffs0 = (uint32_t)ar * 64u + ((uint32_t)((ac0 + 0) ^ arx) << 4) + 0u;
    const uint32_t aoffs1 = (uint32_t)ar * 64u + ((uint32_t)((ac0 + 0) ^ arx) << 4) + 8u;
    const uint32_t aoffs2 = (uint32_t)ar * 64u + ((uint32_t)((ac0 + 1) ^ arx) << 4) + 0u;
    const uint32_t aoffs3 = (uint32_t)ar * 64u + ((uint32_t)((ac0 + 1) ^ arx) << 4) + 8u;
    const int bc0 = (tid & 7) * 2;
    const int bkx = bkr & 7;
    const uint32_t boffs0 = (uint32_t)bkr * 256u + ((uint32_t)((bc0 + 0) ^ bkx) << 4) + 0u;
    const uint32_t boffs1 = (uint32_t)bkr * 256u + ((uint32_t)((bc0 + 0) ^ bkx) << 4) + 8u;
    const uint32_t boffs2 = (uint32_t)bkr * 256u + ((uint32_t)((bc0 + 1) ^ bkx) << 4) + 0u;
    const uint32_t boffs3 = (uint32_t)bkr * 256u + ((uint32_t)((bc0 + 1) ^ bkx) << 4) + 8u;

    bool aValid = true;
    const float* pA;
    if (FIRST) {
        const int si = s_src[ar];
        aValid = si >= 0;
        pA = x + (aValid ? (size_t)si * K : 0) + kA;
    } else {
        pA = g_h + (size_t)(row0 + ar) * K + kA;
    }
    const float* pB = W + (size_t)e * K * NF + (size_t)bkr * NF + n0 + bnb;

    float4 av0 = make_float4(0.f,0.f,0.f,0.f), av1 = av0, av2 = av0, av3 = av0;
    float4 bv0, bv1, bv2, bv3;

    // ---- accumulators: 2 mt x 8 nt x 4, named scalars ----
#define DECL8(nt_) float c0_##nt_##_0=0.f,c0_##nt_##_1=0.f,c0_##nt_##_2=0.f,c0_##nt_##_3=0.f, \
                        c1_##nt_##_0=0.f,c1_##nt_##_1=0.f,c1_##nt_##_2=0.f,c1_##nt_##_3=0.f
    DECL8(0); DECL8(1); DECL8(2); DECL8(3); DECL8(4); DECL8(5); DECL8(6); DECL8(7);
#undef DECL8
    uint32_t a0, a1, a2, a3;
    uint32_t b0_0,b0_1,b1_0,b1_1,b2_0,b2_1,b3_0,b3_1;
    uint32_t b4_0,b4_1,b5_0,b5_1,b6_0,b6_1,b7_0,b7_1;

    const uint32_t uAh = smem_u32(sAh), uAl = smem_u32(sAl);
    const uint32_t uBh = smem_u32(sBh), uBl = smem_u32(sBl);

    // ldsm lane components
    const int a_m   = wm * 32 + (lane & 15);
    const int a_k16 = lane >> 4;
    const int b_k   = (lane & 7) + ((lane >> 3) & 1) * 8;
    const int b_ncb = wn * 8 + (lane >> 4);

#define LDA(bu_, mt_, ks_) do {                                                   \
        const int rm_ = a_m + (mt_) * 16;                                         \
        const uint32_t ao_ = (uint32_t)rm_ * 64u                                  \
            + ((uint32_t)((((ks_) * 2 + a_k16) ^ ((rm_ >> 1) & 3))) << 4);        \
        LDSM4(a0, a1, a2, a3, (bu_) + ao_);                                       \
    } while (0)
#define LDB(bu_, ks_, g_, p_, q_) do {                                            \
        const int bk_ = (ks_) * 16 + b_k;                                         \
        const uint32_t bo_ = (uint32_t)bk_ * 256u                                 \
            + ((uint32_t)(((b_ncb + (g_) * 2) ^ (bk_ & 7))) << 4);                \
        LDSM4T(p_##_0, p_##_1, q_##_0, q_##_1, (bu_) + bo_);                      \
    } while (0)

    // preload chunk 0
    if (aValid) {
        av0 = *(const float4*)(pA);      av1 = *(const float4*)(pA + 4);
        av2 = *(const float4*)(pA + 8);  av3 = *(const float4*)(pA + 12);
    }
    bv0 = *(const float4*)(pB);      bv1 = *(const float4*)(pB + 4);
    bv2 = *(const float4*)(pB + 8);  bv3 = *(const float4*)(pB + 12);

    for (int kc = 0; kc < NC; ++kc) {
        __syncthreads();
        STS_SPLIT(av0, aoffs0, sAh, sAl);
        STS_SPLIT(av1, aoffs1, sAh, sAl);
        STS_SPLIT(av2, aoffs2, sAh, sAl);
        STS_SPLIT(av3, aoffs3, sAh, sAl);
        STS_SPLIT(bv0, boffs0, sBh, sBl);
        STS_SPLIT(bv1, boffs1, sBh, sBl);
        STS_SPLIT(bv2, boffs2, sBh, sBl);
        STS_SPLIT(bv3, boffs3, sBh, sBl);
        __syncthreads();
        if (kc + 1 < NC) {
            if (aValid) {
                const float* p_ = pA + (kc + 1) * 32;
                av0 = *(const float4*)(p_);      av1 = *(const float4*)(p_ + 4);
                av2 = *(const float4*)(p_ + 8);  av3 = *(const float4*)(p_ + 12);
            }
            const float* q_ = pB + (size_t)(kc + 1) * 32 * NF;
            bv0 = *(const float4*)(q_);      bv1 = *(const float4*)(q_ + 4);
            bv2 = *(const float4*)(q_ + 8);  bv3 = *(const float4*)(q_ + 12);
        }
        #pragma unroll
        for (int ks = 0; ks < 2; ++ks) {
            // pass 1: ah * bh
            LDB(uBh, ks, 0, b0, b1); LDB(uBh, ks, 1, b2, b3);
            LDB(uBh, ks, 2, b4, b5); LDB(uBh, ks, 3, b6, b7);
            LDA(uAh, 0, ks); MMA_ALLNT(0);
            LDA(uAh, 1, ks); MMA_ALLNT(1);
            // pass 2: al * bh
            LDA(uAl, 0, ks); MMA_ALLNT(0);
            LDA(uAl, 1, ks); MMA_ALLNT(1);
            // pass 3: ah * bl
            LDB(uBl, ks, 0, b0, b1); LDB(uBl, ks, 1, b2, b3);
            LDB(uBl, ks, 2, b4, b5); LDB(uBl, ks, 3, b6, b7);
            LDA(uAh, 0, ks); MMA_ALLNT(0);
            LDA(uAh, 1, ks); MMA_ALLNT(1);
        }
    }

    // ---- epilogue ----
    const float* be = bias + (size_t)e * NF + n0;
#define EPI(mt_, nt_) do {                                                        \
        const int ra_ = row0 + wm * 32 + (mt_) * 16 + (lane >> 2);                \
        const int cl_ = wn * 64 + (nt_) * 8 + (lane & 3) * 2;                     \
        const float bb0_ = be[cl_], bb1_ = be[cl_ + 1];                           \
        float u0_ = c##mt_##_##nt_##_0 + bb0_;                                    \
        float u1_ = c##mt_##_##nt_##_1 + bb1_;                                    \
        float u2_ = c##mt_##_##nt_##_2 + bb0_;                                    \
        float u3_ = c##mt_##_##nt_##_3 + bb1_;                                    \
        if (FIRST) { u0_ = fmaxf(u0_, 0.f); u1_ = fmaxf(u1_, 0.f);                \
                     u2_ = fmaxf(u2_, 0.f); u3_ = fmaxf(u3_, 0.f); }              \
        float* op_ = FIRST ? g_h : g_eo;                                          \
        *(float2*)(op_ + (size_t)ra_ * NF + n0 + cl_) = make_float2(u0_, u1_);    \
        *(float2*)(op_ + (size_t)(ra_ + 8) * NF + n0 + cl_) = make_float2(u2_, u3_); \
    } while (0)
    EPI(0,0); EPI(0,1); EPI(0,2); EPI(0,3); EPI(0,4); EPI(0,5); EPI(0,6); EPI(0,7);
    EPI(1,0); EPI(1,1); EPI(1,2); EPI(1,3); EPI(1,4); EPI(1,5); EPI(1,6); EPI(1,7);
#undef EPI
}

// ---------------- K5: combine ----------------
__global__ void __launch_bounds__(256) k_combine(float* __restrict__ y) {
    const int tid = threadIdx.x, w = tid >> 5, lane = tid & 31;
    const int s = blockIdx.x * 8 + w;
    const int sl0 = g_slot[2 * s], sl1 = g_slot[2 * s + 1];
    const float w0 = g_wcomb[2 * s], w1 = g_wcomb[2 * s + 1];
    const float4* e0 = (const float4*)(g_eo + (size_t)sl0 * kM);
    const float4* e1 = (const float4*)(g_eo + (size_t)sl1 * kM);
    float4* yr = (float4*)(y + (size_t)s * kM);
    #pragma unroll
    for (int r = 0; r < 2; ++r) {
        const int j = lane * 2 + r;
        const float4 u = e0[j], v = e1[j];
        yr[j] = make_float4(w0 * u.x + w1 * v.x, w0 * u.y + w1 * v.y,
                            w0 * u.z + w1 * v.z, w0 * u.w + w1 * v.w);
    }
}

// ---------------- launcher (round-1 profile: no attrs, no dyn smem) ----------------
extern "C" void kernel_launch(void* const* d_in, const int* in_sizes, int n_in,
                              void* d_out, int out_size) {
    const float* x  = (const float*)d_in[0];
    const float* wg = (const float*)d_in[1];
    const float* w1 = (const float*)d_in[2];
    const float* b1 = (const float*)d_in[3];
    const float* w2 = (const float*)d_in[4];
    const float* b2 = (const float*)d_in[5];
    float* out = (float*)d_out;

    k_init<<<kECAP / 256, 256>>>();
    k_gate<<<kNB, 256>>>(x, wg);
    k_scan<<<1, 256>>>(out, out_size);
    k_locs<<<kNB, 256>>>();

    dim3 g1(kH / 128, kECAP / 128);   // (8, 1280)
    k_ffn_mma<true><<<g1, 256>>>(w1, b1, x);
    dim3 g2(kM / 128, kECAP / 128);   // (2, 1280)
    k_ffn_mma<false><<<g2, 256>>>(w2, b2, x);

    k_combine<<<kS / 8, 256>>>(out);
}